// round 15
// baseline (speedup 1.0000x reference)
#include <cuda_runtime.h>
#include <cuda_bf16.h>
#include <math.h>
#include <stdint.h>

// ---------------------------------------------------------------- shapes
#define B_   16
#define T_   2048
#define D_   1024
#define V_   640
#define M_   (B_ * T_)        // 32768 rows

#define QS      25.4f          // int8 quant scale (clip at ~5 sigma)
#define DESCALE (1.0f / (QS * QS))
#define DELTA   4.5f           // candidate margin (~6.2 sigma pairwise int8 error)
#define MAXC    24

// GEMM tiling
#define BMT   128              // CTA rows
#define BNT   128              // N chunk (5 chunks cover V=640)
#define KT    256              // k elems (s8) per stage = 256B rows
#define NTH   256
#define NCHUNK (V_ / BNT)      // 5
#define NKT   (D_ / KT)        // 4 tiles per chunk
#define NT_TOT (NCHUNK * NKT)  // 20 global tiles

// dynamic SMEM layout (bytes)
#define SM_A    0              // 2 stages x 32768
#define SM_B    65536          // 2 stages x 32768
#define SM_SC   131072         // float[128*132] = 67584 (gumbel staged + scores)
#define SMEM_TOTAL 198656

// ---------------------------------------------------------------- scratch
__device__ int     g_idx[M_];
__device__ int8_t  g_z8[M_ * D_];
__device__ int8_t  g_cb8[V_ * D_];
__device__ int     g_ncand[M_];
__device__ int     g_cand[M_][MAXC];

// ---------------------------------------------------------------- PTX helpers
__device__ __forceinline__ uint32_t smem_u32(const void* p) {
    uint32_t a;
    asm("{ .reg .u64 t; cvta.to.shared.u64 t, %1; cvt.u32.u64 %0, t; }" : "=r"(a) : "l"(p));
    return a;
}
#define CP16(dst, src) \
    asm volatile("cp.async.cg.shared.global [%0], [%1], 16;" :: "r"(dst), "l"(src) : "memory")
#define CP_COMMIT() asm volatile("cp.async.commit_group;" ::: "memory")
#define CP_WAIT1()  asm volatile("cp.async.wait_group 1;" ::: "memory")

#define LDMX4(r, a) \
    asm volatile("ldmatrix.sync.aligned.m8n8.x4.shared.b16 {%0,%1,%2,%3}, [%4];" \
        : "=r"((r)[0]), "=r"((r)[1]), "=r"((r)[2]), "=r"((r)[3]) : "r"(a))

// int8 IMMA: m16n8k32, s32 accum. Fragment byte-layout matches the bf16 k16
// path reinterpreted (16B units), so ldmatrix addressing is unchanged.
#define MMAI(d, a, b0, b1) \
    asm volatile("mma.sync.aligned.m16n8k32.row.col.s32.s8.s8.s32 " \
        "{%0,%1,%2,%3}, {%4,%5,%6,%7}, {%8,%9}, {%0,%1,%2,%3};" \
        : "+r"((d)[0]), "+r"((d)[1]), "+r"((d)[2]), "+r"((d)[3]) \
        : "r"((a)[0]), "r"((a)[1]), "r"((a)[2]), "r"((a)[3]), "r"(b0), "r"(b1))

// ---------------------------------------------------------------- f32 -> s8 quantize (z and cb fused)
__device__ __forceinline__ uint32_t q4(float a, float b, float c, float d) {
    int i0 = min(127, max(-127, __float2int_rn(a * QS)));
    int i1 = min(127, max(-127, __float2int_rn(b * QS)));
    int i2 = min(127, max(-127, __float2int_rn(c * QS)));
    int i3 = min(127, max(-127, __float2int_rn(d * QS)));
    return (uint32_t)(i0 & 255) | ((uint32_t)(i1 & 255) << 8) |
           ((uint32_t)(i2 & 255) << 16) | ((uint32_t)(i3 & 255) << 24);
}
#define NZ8 (M_ * D_ / 8)      // uint2 outputs for z
#define NC8 (V_ * D_ / 8)      // uint2 outputs for cb
__global__ __launch_bounds__(256) void cvt_kernel(
    const float* __restrict__ z, const float* __restrict__ cb)
{
    size_t i = (size_t)blockIdx.x * 256 + threadIdx.x;
    if (i < NZ8) {
        const float4* p = (const float4*)z + i * 2;
        float4 v0 = p[0], v1 = p[1];
        ((uint2*)g_z8)[i] = make_uint2(q4(v0.x, v0.y, v0.z, v0.w),
                                       q4(v1.x, v1.y, v1.z, v1.w));
    } else if (i < NZ8 + NC8) {
        size_t j = i - NZ8;
        const float4* p = (const float4*)cb + j * 2;
        float4 v0 = p[0], v1 = p[1];
        ((uint2*)g_cb8)[j] = make_uint2(q4(v0.x, v0.y, v0.z, v0.w),
                                        q4(v1.x, v1.y, v1.z, v1.w));
    }
}

// ---------------------------------------------------------------- GEMM + candidates
// grid 256 CTAs, 256 threads (8 warps, 32x64 warp tiles). 5 N-chunks of 128.
// approx score = (s8 dot)*DESCALE + gumbel; keep all v within DELTA of row max.
__device__ __forceinline__ void load_tile(uint32_t smb, int m0, int gt) {
    if (gt < NT_TOT) {
        const int ch = gt >> 2, tt = gt & 3;
        const int n0 = ch * BNT, k0 = tt * KT;
        const int stage = gt & 1;
        const int tid = threadIdx.x;
#pragma unroll
        for (int r = 0; r < 8; r++) {
            int p = tid + r * NTH;          // 0..2047
            int row = p >> 4, c16 = p & 15;
            uint32_t sw = (uint32_t)((c16 ^ (row & 7)) << 4);
            CP16(smb + SM_A + stage * 32768 + row * 256 + sw,
                 g_z8 + (size_t)(m0 + row) * D_ + k0 + c16 * 16);
            CP16(smb + SM_B + stage * 32768 + row * 256 + sw,
                 g_cb8 + (size_t)(n0 + row) * D_ + k0 + c16 * 16);
        }
    }
}
__device__ __forceinline__ void load_gumbel(uint32_t smb, const float* gum, int m0, int v0) {
    const int tid = threadIdx.x;
#pragma unroll
    for (int r = 0; r < 16; r++) {
        int p = tid + r * NTH;              // 0..4095
        int row = p >> 5, c4 = p & 31;
        CP16(smb + SM_SC + row * 528 + c4 * 16,
             gum + (size_t)(m0 + row) * V_ + v0 + c4 * 4);
    }
}

__global__ __launch_bounds__(NTH, 1) void gemm_cand_kernel(const float* __restrict__ gum)
{
    extern __shared__ char sm[];
    float* scb = (float*)(sm + SM_SC);
    const uint32_t smb = smem_u32(sm);
    const int tid  = threadIdx.x;
    const int lane = tid & 31;
    const int wid  = tid >> 5;
    const int wm   = (wid & 3) * 32;     // warp row base (4 over 128 M)
    const int wn   = (wid >> 2) * 64;    // warp col base (2 over 128 N)
    const int m0   = blockIdx.x * BMT;

    // per-row candidate state (owner threads tid < 128, one row each)
    float bestv = -1e30f;
    float cs[MAXC];
    int   cvd[MAXC];
    int   nc = 0, ovf = 0;

    load_tile(smb, m0, 0); CP_COMMIT();
    load_tile(smb, m0, 1); CP_COMMIT();

    for (int ch = 0; ch < NCHUNK; ch++) {
        const int v0 = ch * BNT;
        int acc[2][8][4];
#pragma unroll
        for (int mi = 0; mi < 2; mi++)
#pragma unroll
            for (int nj = 0; nj < 8; nj++)
#pragma unroll
                for (int q = 0; q < 4; q++) acc[mi][nj][q] = 0;

        for (int lt = 0; lt < NKT; lt++) {
            const int gt = ch * NKT + lt;
            const int s  = gt & 1;
            CP_WAIT1();
            __syncthreads();

            const uint32_t sa = smb + SM_A + s * 32768;
            const uint32_t sb = smb + SM_B + s * 32768;
#pragma unroll
            for (int kk = 0; kk < 8; kk++) {               // 8 x k32 per 256-elem tile
                const int csel = kk * 2 + (lane >> 4);     // 16B chunk in 256B row
                const int rsel = lane & 15;
                uint32_t a[2][4], bb[4][4];
#pragma unroll
                for (int mi = 0; mi < 2; mi++) {
                    int row = wm + mi * 16 + rsel;
                    LDMX4(a[mi], sa + row * 256 + ((csel ^ (row & 7)) << 4));
                }
#pragma unroll
                for (int g = 0; g < 4; g++) {
                    int row = wn + g * 16 + rsel;
                    LDMX4(bb[g], sb + row * 256 + ((csel ^ (row & 7)) << 4));
                }
#pragma unroll
                for (int mi = 0; mi < 2; mi++)
#pragma unroll
                    for (int g = 0; g < 4; g++) {
                        MMAI(acc[mi][2 * g],     a[mi], bb[g][0], bb[g][2]);
                        MMAI(acc[mi][2 * g + 1], a[mi], bb[g][1], bb[g][3]);
                    }
            }
            __syncthreads();
            // prefetch tile gt+2 into stage s (just consumed); gumbel piggybacks
            // on the group committed at lt == NKT-3 (complete by lt == NKT-1's wait)
            load_tile(smb, m0, gt + 2);
            if (lt == NKT - 3) load_gumbel(smb, gum, m0, v0);
            CP_COMMIT();
        }

        // ---- epilogue: scb already holds gumbel; descale + add in place ----
#pragma unroll
        for (int mi = 0; mi < 2; mi++)
#pragma unroll
            for (int nj = 0; nj < 8; nj++) {
                int lr = wm + mi * 16 + (lane >> 2);
                int lc = wn + nj * 8 + ((lane & 3) << 1);
                float2* p0 = (float2*)&scb[lr * 132 + lc];
                float2* p1 = (float2*)&scb[(lr + 8) * 132 + lc];
                float2 g0 = *p0, g1 = *p1;
                *p0 = make_float2(fmaf((float)acc[mi][nj][0], DESCALE, g0.x),
                                  fmaf((float)acc[mi][nj][1], DESCALE, g0.y));
                *p1 = make_float2(fmaf((float)acc[mi][nj][2], DESCALE, g1.x),
                                  fmaf((float)acc[mi][nj][3], DESCALE, g1.y));
            }
        __syncthreads();
        if (tid < BMT) {
            const float* srow = scb + tid * 132;
            // pass 1 (vectorized): chunk max -> fold into global max FIRST
            float cmax = -1e30f;
#pragma unroll 8
            for (int c4 = 0; c4 < 32; c4++) {
                float4 v = *(const float4*)&srow[c4 * 4];
                cmax = fmaxf(cmax, fmaxf(fmaxf(v.x, v.y), fmaxf(v.z, v.w)));
            }
            if (cmax > bestv) bestv = cmax;
            // pass 2: collect within DELTA of updated global max
            const float thr = bestv - DELTA;
            for (int c = 0; c < BNT; c++) {
                float sc = srow[c];
                if (sc > thr) {
                    if (nc < MAXC) { cs[nc] = sc; cvd[nc] = v0 + c; nc++; }
                    else ovf = 1;
                }
            }
        }
        __syncthreads();   // scan done before next chunk's gumbel cp.async lands
    }

    if (tid < BMT) {
        int m = m0 + tid;
        if (ovf) g_ncand[m] = 1000;
        else {
            int o = 0;
            for (int i = 0; i < nc; i++)
                if (cs[i] > bestv - DELTA) g_cand[m][o++] = cvd[i];  // ascending v
            g_ncand[m] = o;
        }
    }
}

// ---------------------------------------------------------------- exact rescore + gather (warp per row)
__global__ __launch_bounds__(256) void rescore_gather_kernel(
    const float* __restrict__ z, const float* __restrict__ cb,
    const float* __restrict__ gum, const float* __restrict__ Wp,
    float* __restrict__ out)
{
    const int lane = threadIdx.x & 31;
    const int wid  = threadIdx.x >> 5;
    const int m    = blockIdx.x * 8 + wid;

    int nc = g_ncand[m];
    int bidx;
    if (nc == 1) {
        bidx = g_cand[m][0];              // unique candidate == exact argmax
    } else {
        float4 zv[8];
        const float4* zr = (const float4*)(z + (size_t)m * D_);
#pragma unroll
        for (int j = 0; j < 8; j++) zv[j] = zr[j * 32 + lane];

        bool full = (nc > MAXC) || (nc <= 0);
        int n = full ? V_ : nc;
        float best = -1e30f;
        bidx = 0;
        for (int i = 0; i < n; i++) {
            int v = full ? i : g_cand[m][i];
            const float4* cr = (const float4*)(cb + (size_t)v * D_);
            float p = 0.0f;
#pragma unroll
            for (int j = 0; j < 8; j++) {
                float4 c = cr[j * 32 + lane];
                p = fmaf(zv[j].x, c.x, p); p = fmaf(zv[j].y, c.y, p);
                p = fmaf(zv[j].z, c.z, p); p = fmaf(zv[j].w, c.w, p);
            }
#pragma unroll
            for (int o = 16; o; o >>= 1) p += __shfl_down_sync(0xffffffffu, p, o);
            float sc = __shfl_sync(0xffffffffu, p, 0) + gum[(size_t)m * V_ + v];
            if (sc > best) { best = sc; bidx = v; }   // ascending v, strict > => first max
        }
    }
    if (lane == 0) g_idx[m] = bidx;
    // gather: copy W_p row bidx -> out row m (coalesced float4 writes)
    const float4* src = (const float4*)(Wp + (size_t)bidx * D_);
    float4* dst = (float4*)(out + (size_t)m * D_);
#pragma unroll
    for (int j = 0; j < 8; j++) dst[j * 32 + lane] = src[j * 32 + lane];
}

// ---------------------------------------------------------------- entropy + loss (single kernel)
__global__ __launch_bounds__(1024) void entropy_loss_kernel(float* __restrict__ out, int off)
{
    __shared__ float s[1024];
    float sum = 0.0f;
#pragma unroll
    for (int r = 0; r < 2; r++) {
        int t = threadIdx.x + r * 1024;
        int ids[B_];
#pragma unroll
        for (int b = 0; b < B_; b++) ids[b] = g_idx[b * T_ + t];
        float H = 0.0f;
#pragma unroll
        for (int b = 0; b < B_; b++) {
            bool first = true;
#pragma unroll
            for (int b2 = 0; b2 < B_; b2++)
                if (b2 < b && ids[b2] == ids[b]) first = false;
            if (first) {
                int c = 0;
#pragma unroll
                for (int b2 = 0; b2 < B_; b2++) c += (ids[b2] == ids[b]);
                float p = (float)c * (1.0f / (float)B_);
                H -= p * logf(p + 1e-10f);
            }
        }
        sum += H;
    }
    s[threadIdx.x] = sum;
    __syncthreads();
    for (int stride = 512; stride > 0; stride >>= 1) {
        if (threadIdx.x < stride) s[threadIdx.x] += s[threadIdx.x + stride];
        __syncthreads();
    }
    if (threadIdx.x == 0 && off >= 0) out[off] = s[0] / (float)T_;
}

// ----------------------------------------------------------------
extern "C" void kernel_launch(void* const* d_in, const int* in_sizes, int n_in,
                              void* d_out, int out_size)
{
    const float* z   = (const float*)d_in[0];  // [B,T,D]
    const float* cb  = (const float*)d_in[1];  // [V,D]
    const float* Wp  = (const float*)d_in[2];  // [V,D]
    const float* gum = (const float*)d_in[3];  // [B,T,V]
    float* out = (float*)d_out;

    cudaFuncSetAttribute(gemm_cand_kernel,
                         cudaFuncAttributeMaxDynamicSharedMemorySize, SMEM_TOTAL);

    cvt_kernel<<<(NZ8 + NC8 + 255) / 256, 256>>>(z, cb);
    gemm_cand_kernel<<<M_ / BMT, NTH, SMEM_TOTAL>>>(gum);
    rescore_gather_kernel<<<M_ / 8, 256>>>(z, cb, gum, Wp, out);
    int off = (out_size > M_ * D_) ? (out_size - 1) : -1;
    entropy_loss_kernel<<<1, 1024>>>(out, off);
}

// round 17
// speedup vs baseline: 1.7782x; 1.7782x over previous
#include <cuda_runtime.h>
#include <cuda_bf16.h>
#include <math.h>
#include <stdint.h>

// ---------------------------------------------------------------- shapes
#define B_   16
#define T_   2048
#define D_   1024
#define V_   640
#define M_   (B_ * T_)        // 32768 rows

#define DELTA 1.5f            // candidate margin (~30-50 sigma of bf16 GEMM error)
#define MAXC  16

// GEMM tiling (round-10 champion config)
#define BMT   128              // CTA rows
#define BNT   128              // N chunk (5 chunks cover V=640)
#define KT    128              // k elems per stage (256B rows)
#define NTH   256
#define NCHUNK (V_ / BNT)      // 5
#define NKT   (D_ / KT)        // 8 tiles per chunk
#define NT_TOT (NCHUNK * NKT)  // 40 global tiles

// dynamic SMEM layout (bytes)
#define SM_A    0              // 2 stages x 32768
#define SM_B    65536          // 2 stages x 32768
#define SM_SC   131072         // float[128*132] = 67584 (gumbel staged + scores)
#define SMEM_TOTAL 198656

// ---------------------------------------------------------------- scratch
__device__ int           g_idx[M_];
__device__ __nv_bfloat16 g_z16[M_ * D_];
__device__ __nv_bfloat16 g_cb16[V_ * D_];
__device__ int           g_ncand[M_];
__device__ int           g_cand[M_][MAXC];

// ---------------------------------------------------------------- PTX helpers
__device__ __forceinline__ uint32_t smem_u32(const void* p) {
    uint32_t a;
    asm("{ .reg .u64 t; cvta.to.shared.u64 t, %1; cvt.u32.u64 %0, t; }" : "=r"(a) : "l"(p));
    return a;
}
__device__ __forceinline__ uint32_t bf2(float lo, float hi) {
    uint32_t r;  // d.hi = cvt(first src), d.lo = cvt(second src)
    asm("cvt.rn.bf16x2.f32 %0, %1, %2;" : "=r"(r) : "f"(hi), "f"(lo));
    return r;
}
#define CP16(dst, src) \
    asm volatile("cp.async.cg.shared.global [%0], [%1], 16;" :: "r"(dst), "l"(src) : "memory")
#define CP_COMMIT() asm volatile("cp.async.commit_group;" ::: "memory")
#define CP_WAIT1()  asm volatile("cp.async.wait_group 1;" ::: "memory")

#define LDMX4(r, a) \
    asm volatile("ldmatrix.sync.aligned.m8n8.x4.shared.b16 {%0,%1,%2,%3}, [%4];" \
        : "=r"((r)[0]), "=r"((r)[1]), "=r"((r)[2]), "=r"((r)[3]) : "r"(a))

#define MMA16816(d, a, b0, b1) \
    asm volatile("mma.sync.aligned.m16n8k16.row.col.f32.bf16.bf16.f32 " \
        "{%0,%1,%2,%3}, {%4,%5,%6,%7}, {%8,%9}, {%0,%1,%2,%3};" \
        : "+f"((d)[0]), "+f"((d)[1]), "+f"((d)[2]), "+f"((d)[3]) \
        : "r"((a)[0]), "r"((a)[1]), "r"((a)[2]), "r"((a)[3]), "r"(b0), "r"(b1))

// ---------------------------------------------------------------- f32 -> bf16 convert (z and cb fused)
#define NZ4 (M_ * D_ / 8)      // uint4 outputs for z
#define NC4 (V_ * D_ / 8)      // uint4 outputs for cb
__global__ __launch_bounds__(256) void cvt_kernel(
    const float* __restrict__ z, const float* __restrict__ cb)
{
    size_t i = (size_t)blockIdx.x * 256 + threadIdx.x;
    if (i < NZ4) {
        const float4* p = (const float4*)z + i * 2;
        float4 v0 = p[0], v1 = p[1];
        ((uint4*)g_z16)[i] = make_uint4(bf2(v0.x, v0.y), bf2(v0.z, v0.w),
                                        bf2(v1.x, v1.y), bf2(v1.z, v1.w));
    } else if (i < NZ4 + NC4) {
        size_t j = i - NZ4;
        const float4* p = (const float4*)cb + j * 2;
        float4 v0 = p[0], v1 = p[1];
        ((uint4*)g_cb16)[j] = make_uint4(bf2(v0.x, v0.y), bf2(v0.z, v0.w),
                                         bf2(v1.x, v1.y), bf2(v1.z, v1.w));
    }
}

// ---------------------------------------------------------------- GEMM + candidates
// grid 256 CTAs, 256 threads (8 warps, 32x64 warp tiles). 5 N-chunks of 128.
// approx score = bf16(z).bf16(cb) + gumbel; keep all v within DELTA of row max.
__device__ __forceinline__ void load_tile(uint32_t smb, int m0, int gt) {
    if (gt < NT_TOT) {
        const int ch = gt >> 3, tt = gt & 7;
        const int n0 = ch * BNT, k0 = tt * KT;
        const int stage = gt & 1;
        const int tid = threadIdx.x;
#pragma unroll
        for (int r = 0; r < 8; r++) {
            int p = tid + r * NTH;          // 0..2047
            int row = p >> 4, c16 = p & 15;
            uint32_t sw = (uint32_t)((c16 ^ (row & 7)) << 4);
            CP16(smb + SM_A + stage * 32768 + row * 256 + sw,
                 g_z16 + (size_t)(m0 + row) * D_ + k0 + c16 * 8);
            CP16(smb + SM_B + stage * 32768 + row * 256 + sw,
                 g_cb16 + (size_t)(n0 + row) * D_ + k0 + c16 * 8);
        }
    }
}
__device__ __forceinline__ void load_gumbel(uint32_t smb, const float* gum, int m0, int v0) {
    const int tid = threadIdx.x;
#pragma unroll
    for (int r = 0; r < 16; r++) {
        int p = tid + r * NTH;              // 0..4095
        int row = p >> 5, c4 = p & 31;
        CP16(smb + SM_SC + row * 528 + c4 * 16,
             gum + (size_t)(m0 + row) * V_ + v0 + c4 * 4);
    }
}

__global__ __launch_bounds__(NTH, 1) void gemm_cand_kernel(const float* __restrict__ gum)
{
    extern __shared__ char sm[];
    float* scb = (float*)(sm + SM_SC);
    const uint32_t smb = smem_u32(sm);
    const int tid  = threadIdx.x;
    const int lane = tid & 31;
    const int wid  = tid >> 5;
    const int wm   = (wid & 3) * 32;     // warp row base (4 over 128 M)
    const int wn   = (wid >> 2) * 64;    // warp col base (2 over 128 N)
    const int m0   = blockIdx.x * BMT;

    // per-row candidate state (owner threads tid < 128, one row each)
    float bestv = -1e30f;
    float cs[MAXC];
    int   cvd[MAXC];
    int   nc = 0, ovf = 0;

    load_tile(smb, m0, 0); CP_COMMIT();
    load_tile(smb, m0, 1); CP_COMMIT();

    for (int ch = 0; ch < NCHUNK; ch++) {
        const int v0 = ch * BNT;
        float acc[2][8][4];
#pragma unroll
        for (int mi = 0; mi < 2; mi++)
#pragma unroll
            for (int nj = 0; nj < 8; nj++)
#pragma unroll
                for (int q = 0; q < 4; q++) acc[mi][nj][q] = 0.0f;

        for (int lt = 0; lt < NKT; lt++) {
            const int gt = ch * NKT + lt;
            const int s  = gt & 1;
            CP_WAIT1();
            __syncthreads();

            const uint32_t sa = smb + SM_A + s * 32768;
            const uint32_t sb = smb + SM_B + s * 32768;
#pragma unroll
            for (int kk = 0; kk < 8; kk++) {
                const int csel = kk * 2 + (lane >> 4);   // 16B chunk in 256B row
                const int rsel = lane & 15;
                uint32_t a[2][4], bb[4][4];
#pragma unroll
                for (int mi = 0; mi < 2; mi++) {
                    int row = wm + mi * 16 + rsel;
                    LDMX4(a[mi], sa + row * 256 + ((csel ^ (row & 7)) << 4));
                }
#pragma unroll
                for (int g = 0; g < 4; g++) {
                    int row = wn + g * 16 + rsel;
                    LDMX4(bb[g], sb + row * 256 + ((csel ^ (row & 7)) << 4));
                }
#pragma unroll
                for (int mi = 0; mi < 2; mi++)
#pragma unroll
                    for (int g = 0; g < 4; g++) {
                        MMA16816(acc[mi][2 * g],     a[mi], bb[g][0], bb[g][2]);
                        MMA16816(acc[mi][2 * g + 1], a[mi], bb[g][1], bb[g][3]);
                    }
            }
            __syncthreads();
            // prefetch tile gt+2 into stage s (just consumed); gumbel piggybacks
            // on the group committed at lt == NKT-3 (complete by lt == NKT-1's wait)
            load_tile(smb, m0, gt + 2);
            if (lt == NKT - 3) load_gumbel(smb, gum, m0, v0);
            CP_COMMIT();
        }

        // ---- epilogue: scb already holds gumbel; add fragments in place ----
#pragma unroll
        for (int mi = 0; mi < 2; mi++)
#pragma unroll
            for (int nj = 0; nj < 8; nj++) {
                int lr = wm + mi * 16 + (lane >> 2);
                int lc = wn + nj * 8 + ((lane & 3) << 1);
                float2* p0 = (float2*)&scb[lr * 132 + lc];
                float2* p1 = (float2*)&scb[(lr + 8) * 132 + lc];
                float2 g0 = *p0, g1 = *p1;
                *p0 = make_float2(acc[mi][nj][0] + g0.x, acc[mi][nj][1] + g0.y);
                *p1 = make_float2(acc[mi][nj][2] + g1.x, acc[mi][nj][3] + g1.y);
            }
        __syncthreads();
        if (tid < BMT) {
            const float* srow = scb + tid * 132;
            // pass 1 (vectorized): chunk max -> fold into global max FIRST
            float cmax = -1e30f;
#pragma unroll 8
            for (int c4 = 0; c4 < 32; c4++) {
                float4 v = *(const float4*)&srow[c4 * 4];
                cmax = fmaxf(cmax, fmaxf(fmaxf(v.x, v.y), fmaxf(v.z, v.w)));
            }
            if (cmax > bestv) bestv = cmax;
            // pass 2: collect within DELTA of updated global max
            const float thr = bestv - DELTA;
            for (int c = 0; c < BNT; c++) {
                float sc = srow[c];
                if (sc > thr) {
                    if (nc < MAXC) { cs[nc] = sc; cvd[nc] = v0 + c; nc++; }
                    else ovf = 1;
                }
            }
        }
        __syncthreads();   // scan done before next chunk's gumbel cp.async lands
    }

    if (tid < BMT) {
        int m = m0 + tid;
        if (ovf) g_ncand[m] = 1000;
        else {
            int o = 0;
            for (int i = 0; i < nc; i++)
                if (cs[i] > bestv - DELTA) g_cand[m][o++] = cvd[i];  // ascending v
            g_ncand[m] = o;
        }
    }
}

// ---------------------------------------------------------------- exact rescore + gather (warp per row)
__global__ __launch_bounds__(256) void rescore_gather_kernel(
    const float* __restrict__ z, const float* __restrict__ cb,
    const float* __restrict__ gum, const float* __restrict__ Wp,
    float* __restrict__ out)
{
    const int lane = threadIdx.x & 31;
    const int wid  = threadIdx.x >> 5;
    const int m    = blockIdx.x * 8 + wid;

    int nc = g_ncand[m];
    int bidx;
    if (nc == 1) {
        bidx = g_cand[m][0];              // unique candidate == exact argmax
    } else {
        float4 zv[8];
        const float4* zr = (const float4*)(z + (size_t)m * D_);
#pragma unroll
        for (int j = 0; j < 8; j++) zv[j] = zr[j * 32 + lane];

        bool full = (nc > MAXC) || (nc <= 0);
        int n = full ? V_ : nc;
        float best = -1e30f;
        bidx = 0;
        for (int i = 0; i < n; i++) {
            int v = full ? i : g_cand[m][i];
            const float4* cr = (const float4*)(cb + (size_t)v * D_);
            float p = 0.0f;
#pragma unroll
            for (int j = 0; j < 8; j++) {
                float4 c = cr[j * 32 + lane];
                p = fmaf(zv[j].x, c.x, p); p = fmaf(zv[j].y, c.y, p);
                p = fmaf(zv[j].z, c.z, p); p = fmaf(zv[j].w, c.w, p);
            }
#pragma unroll
            for (int o = 16; o; o >>= 1) p += __shfl_down_sync(0xffffffffu, p, o);
            float sc = __shfl_sync(0xffffffffu, p, 0) + gum[(size_t)m * V_ + v];
            if (sc > best) { best = sc; bidx = v; }   // ascending v, strict > => first max
        }
    }
    if (lane == 0) g_idx[m] = bidx;
    // gather: copy W_p row bidx -> out row m (coalesced float4 writes)
    const float4* src = (const float4*)(Wp + (size_t)bidx * D_);
    float4* dst = (float4*)(out + (size_t)m * D_);
#pragma unroll
    for (int j = 0; j < 8; j++) dst[j * 32 + lane] = src[j * 32 + lane];
}

// ---------------------------------------------------------------- entropy + loss (single kernel)
__global__ __launch_bounds__(1024) void entropy_loss_kernel(float* __restrict__ out, int off)
{
    __shared__ float s[1024];
    float sum = 0.0f;
#pragma unroll
    for (int r = 0; r < 2; r++) {
        int t = threadIdx.x + r * 1024;
        int ids[B_];
#pragma unroll
        for (int b = 0; b < B_; b++) ids[b] = g_idx[b * T_ + t];
        float H = 0.0f;
#pragma unroll
        for (int b = 0; b < B_; b++) {
            bool first = true;
#pragma unroll
            for (int b2 = 0; b2 < B_; b2++)
                if (b2 < b && ids[b2] == ids[b]) first = false;
            if (first) {
                int c = 0;
#pragma unroll
                for (int b2 = 0; b2 < B_; b2++) c += (ids[b2] == ids[b]);
                float p = (float)c * (1.0f / (float)B_);
                H -= p * logf(p + 1e-10f);
            }
        }
        sum += H;
    }
    s[threadIdx.x] = sum;
    __syncthreads();
    for (int stride = 512; stride > 0; stride >>= 1) {
        if (threadIdx.x < stride) s[threadIdx.x] += s[threadIdx.x + stride];
        __syncthreads();
    }
    if (threadIdx.x == 0 && off >= 0) out[off] = s[0] / (float)T_;
}

// ----------------------------------------------------------------
extern "C" void kernel_launch(void* const* d_in, const int* in_sizes, int n_in,
                              void* d_out, int out_size)
{
    const float* z   = (const float*)d_in[0];  // [B,T,D]
    const float* cb  = (const float*)d_in[1];  // [V,D]
    const float* Wp  = (const float*)d_in[2];  // [V,D]
    const float* gum = (const float*)d_in[3];  // [B,T,V]
    float* out = (float*)d_out;

    cudaFuncSetAttribute(gemm_cand_kernel,
                         cudaFuncAttributeMaxDynamicSharedMemorySize, SMEM_TOTAL);

    cvt_kernel<<<(NZ4 + NC4 + 255) / 256, 256>>>(z, cb);
    gemm_cand_kernel<<<M_ / BMT, NTH, SMEM_TOTAL>>>(gum);
    rescore_gather_kernel<<<M_ / 8, 256>>>(z, cb, gum, Wp, out);
    int off = (out_size > M_ * D_) ? (out_size - 1) : -1;
    entropy_loss_kernel<<<1, 1024>>>(out, off);
}